// round 4
// baseline (speedup 1.0000x reference)
#include <cuda_runtime.h>
#include <math.h>

#define BDIM 512
#define MAXB 65536

// Scratch (allocation-free): per-row {loss, keep} packed.
__device__ float2       g_row[MAXB];
__device__ unsigned int g_done = 0;

__device__ __forceinline__ float warp_sum(float v) {
#pragma unroll
    for (int o = 16; o > 0; o >>= 1)
        v += __shfl_xor_sync(0xffffffffu, v, o);
    return v;
}

// One block of 512 threads per row; whole 8192-elem row in ONE front-batched
// chunk of 4 LDG.128 per thread. Early tgt + gather loads hide under exp phase.
template <int NL>
__global__ void __launch_bounds__(BDIM)
fused_kernel(const float* __restrict__ prd, const int* __restrict__ tgt,
             float* __restrict__ out, int xc, int B)
{
    static_assert(NL == BDIM * 16, "one-chunk layout: 512 thr x 4 float4");

    __shared__ int   s_lab[64];
    __shared__ float shf[BDIM / 32];
    __shared__ float shs[BDIM / 32];
    __shared__ float shc[BDIM / 32];
    __shared__ int   s_last;

    const int row = blockIdx.x;
    const int tid = threadIdx.x;
    const int w   = tid >> 5;
    const int l   = tid & 31;
    const int X   = xc - 1;

    const float*  p    = prd + (size_t)row * NL;
    const float4* p4   = (const float4*)p;
    const int*    trow = tgt + (size_t)row * xc;

    // ---- 1. tgt loads first (2 cache lines) ----
    int labv = 0;
    if (tid <= X) labv = trow[tid];

    // ---- 2. whole row: 4 unpredicated LDG.128 per thread ----
    float4 b0 = p4[tid];
    float4 b1 = p4[tid + BDIM];
    float4 b2 = p4[tid + 2 * BDIM];
    float4 b3 = p4[tid + 3 * BDIM];

    // ---- 3. publish labels, issue gather load (hides under exp phase) ----
    if (tid <= X) s_lab[tid] = labv;
    __syncthreads();
    int   glab = 0;
    float gval = 0.0f;
    if (tid < X) {
        glab = s_lab[tid];
        if (glab != 0) gval = p[glab];
    }

    // ---- 4. exp phase ----
    float lsum = 0.0f;
    lsum += __expf(b0.x); lsum += __expf(b0.y); lsum += __expf(b0.z); lsum += __expf(b0.w);
    lsum += __expf(b1.x); lsum += __expf(b1.y); lsum += __expf(b1.z); lsum += __expf(b1.w);
    lsum += __expf(b2.x); lsum += __expf(b2.y); lsum += __expf(b2.z); lsum += __expf(b2.w);
    lsum += __expf(b3.x); lsum += __expf(b3.y); lsum += __expf(b3.z); lsum += __expf(b3.w);

    float sel = 0.0f, nzf = 0.0f;
    if (glab != 0) { sel = __expf(gval); nzf = 1.0f; }

    // ---- 5. ONE combined block reduction of (lsum, sel, nz) ----
    float a = warp_sum(lsum);
    float bb = warp_sum(sel);
    float c = warp_sum(nzf);
    if (l == 0) { shf[w] = a; shs[w] = bb; shc[w] = c; }
    __syncthreads();
    if (tid < 32) {
        float x  = (tid < BDIM / 32) ? shf[tid] : 0.0f;
        float y  = (tid < BDIM / 32) ? shs[tid] : 0.0f;
        float cc = (tid < BDIM / 32) ? shc[tid] : 0.0f;
        x  = warp_sum(x);
        y  = warp_sum(y);
        cc = warp_sum(cc);
        if (tid == 0) {
            int num_listed  = s_lab[X];
            int ignored     = X - (int)(cc + 0.5f);
            bool keep       = (num_listed - ignored) > 0;
            float per       = -__logf(y / x + 1e-5f);
            g_row[row] = make_float2(keep ? per : 0.0f, keep ? 1.0f : 0.0f);
        }
    }

    // ---- 6. last-CTA global reduction ----
    if (tid == 0) {
        __threadfence();
        unsigned int n = atomicAdd(&g_done, 1u);
        s_last = (n == (unsigned int)(gridDim.x - 1)) ? 1 : 0;
    }
    __syncthreads();
    if (!s_last) return;
    __threadfence();   // acquire

    float s = 0.0f, c2 = 0.0f;
    const float4* r4 = (const float4*)g_row;   // 2 rows per float4
    const int nv = B >> 1;
#pragma unroll 4
    for (int i = tid; i < nv; i += BDIM) {
        float4 v = r4[i];
        s  += v.x + v.z;
        c2 += v.y + v.w;
    }
    s  = warp_sum(s);
    c2 = warp_sum(c2);
    __syncthreads();
    if (l == 0) { shf[w] = s; shs[w] = c2; }
    __syncthreads();
    if (tid < 32) {
        float x  = (tid < BDIM / 32) ? shf[tid] : 0.0f;
        float cc = (tid < BDIM / 32) ? shs[tid] : 0.0f;
        x  = warp_sum(x);
        cc = warp_sum(cc);
        if (tid == 0) {
            out[0] = x / fmaxf(cc, 1.0f);
            g_done = 0;                      // reset for next graph replay
        }
    }
}

// Generic fallback (any nlabels).
__global__ void __launch_bounds__(BDIM)
fused_generic(const float* __restrict__ prd, const int* __restrict__ tgt,
              float* __restrict__ out, int nlabels, int xc, int B)
{
    __shared__ float shf[BDIM / 32];
    __shared__ float shs[BDIM / 32];
    __shared__ float shc[BDIM / 32];
    __shared__ int   s_last;

    const int row = blockIdx.x;
    const int tid = threadIdx.x;
    const int w   = tid >> 5;
    const int l   = tid & 31;

    const float* p    = prd + (size_t)row * nlabels;
    const int*   trow = tgt + (size_t)row * xc;
    const int    X    = xc - 1;

    float lsum = 0.0f;
    for (int i = tid; i < nlabels; i += BDIM) lsum += __expf(p[i]);

    float sel = 0.0f, nzf = 0.0f;
    for (int j = tid; j < X; j += BDIM) {
        int lab = trow[j];
        if (lab != 0) { sel += __expf(p[lab]); nzf += 1.0f; }
    }

    float a = warp_sum(lsum), b = warp_sum(sel), c = warp_sum(nzf);
    if (l == 0) { shf[w] = a; shs[w] = b; shc[w] = c; }
    __syncthreads();
    if (tid < 32) {
        float x  = (tid < BDIM / 32) ? shf[tid] : 0.0f;
        float y  = (tid < BDIM / 32) ? shs[tid] : 0.0f;
        float cc = (tid < BDIM / 32) ? shc[tid] : 0.0f;
        x = warp_sum(x); y = warp_sum(y); cc = warp_sum(cc);
        if (tid == 0) {
            int num_listed = trow[X];
            int ignored    = X - (int)(cc + 0.5f);
            bool keep      = (num_listed - ignored) > 0;
            float per      = -__logf(y / x + 1e-5f);
            g_row[row] = make_float2(keep ? per : 0.0f, keep ? 1.0f : 0.0f);
        }
    }
    if (tid == 0) {
        __threadfence();
        unsigned int n = atomicAdd(&g_done, 1u);
        s_last = (n == (unsigned int)(gridDim.x - 1)) ? 1 : 0;
    }
    __syncthreads();
    if (!s_last) return;
    __threadfence();

    float s = 0.0f, c2 = 0.0f;
    for (int i = tid; i < B; i += BDIM) {
        float2 v = g_row[i];
        s += v.x; c2 += v.y;
    }
    s = warp_sum(s); c2 = warp_sum(c2);
    __syncthreads();
    if (l == 0) { shf[w] = s; shs[w] = c2; }
    __syncthreads();
    if (tid < 32) {
        float x  = (tid < BDIM / 32) ? shf[tid] : 0.0f;
        float cc = (tid < BDIM / 32) ? shs[tid] : 0.0f;
        x = warp_sum(x); cc = warp_sum(cc);
        if (tid == 0) { out[0] = x / fmaxf(cc, 1.0f); g_done = 0; }
    }
}

extern "C" void kernel_launch(void* const* d_in, const int* in_sizes, int n_in,
                              void* d_out, int out_size)
{
    const float* prd = (const float*)d_in[0];
    const int*   tgt = (const int*)d_in[1];

    const int xc = 51;                               // X=50 labels + count col
    const int B  = in_sizes[1] / xc;
    const int nlabels = (int)((long long)in_sizes[0] / B);

    if (nlabels == 8192)
        fused_kernel<8192><<<B, BDIM>>>(prd, tgt, (float*)d_out, xc, B);
    else
        fused_generic<<<B, BDIM>>>(prd, tgt, (float*)d_out, nlabels, xc, B);
}

// round 5
// speedup vs baseline: 1.0823x; 1.0823x over previous
#include <cuda_runtime.h>
#include <math.h>

#define BDIM 256
#define MAXB 65536

// Scratch (allocation-free): per-row {loss, keep} packed.
__device__ float2       g_row[MAXB];
__device__ unsigned int g_done = 0;

__device__ __forceinline__ float warp_sum(float v) {
#pragma unroll
    for (int o = 16; o > 0; o >>= 1)
        v += __shfl_xor_sync(0xffffffffu, v, o);
    return v;
}

// TWO rows per 256-thread CTA. 16 front-batched unpredicated LDG.128 per
// thread (MLP=16), one label barrier + one gather volley + one reduction
// round amortized over 64KB of streamed data.
template <int NL>
__global__ void __launch_bounds__(BDIM, 3)
fused_kernel(const float* __restrict__ prd, const int* __restrict__ tgt,
             float* __restrict__ out, int xc, int npairs)
{
    static_assert(NL / 4 == BDIM * 8, "row = 8 float4 per thread");

    __shared__ int   s_lab0[64];
    __shared__ int   s_lab1[64];
    __shared__ float sh[6][BDIM / 32];
    __shared__ int   s_last;

    const int pair = blockIdx.x;
    const int tid  = threadIdx.x;
    const int w    = tid >> 5;
    const int l    = tid & 31;
    const int X    = xc - 1;

    const float*  p0  = prd + (size_t)(2 * pair) * NL;
    const float*  p1  = p0 + NL;
    const float4* q0  = (const float4*)p0;
    const float4* q1  = (const float4*)p1;
    const int*    t0  = tgt + (size_t)(2 * pair) * xc;
    const int*    t1  = t0 + xc;

    // ---- 1. tgt loads first (4 cache lines) ----
    int labv = 0;
    if (tid <= X)                 labv = t0[tid];
    else if (tid >= 64 && tid <= 64 + X) labv = t1[tid - 64];

    // ---- 2. stream both rows: 16 unpredicated LDG.128 ----
    float4 a[8], b[8];
#pragma unroll
    for (int k = 0; k < 8; k++) a[k] = q0[tid + k * BDIM];
#pragma unroll
    for (int k = 0; k < 8; k++) b[k] = q1[tid + k * BDIM];

    // ---- 3. publish labels, issue gather loads ----
    if (tid <= X)                 s_lab0[tid] = labv;
    else if (tid >= 64 && tid <= 64 + X) s_lab1[tid - 64] = labv;
    __syncthreads();
    int   glab = 0;
    float gval = 0.0f;
    int   which = 0;          // 0 -> row0, 1 -> row1
    if (tid < X) {
        glab = s_lab0[tid];
        if (glab != 0) gval = p0[glab];
    } else if (tid >= 64 && tid < 64 + X) {
        glab = s_lab1[tid - 64];
        which = 1;
        if (glab != 0) gval = p1[glab];
    }

    // ---- 4. exp phase (hides gather latency) ----
    float lsum0 = 0.0f, lsum1 = 0.0f;
#pragma unroll
    for (int k = 0; k < 8; k++) {
        lsum0 += __expf(a[k].x); lsum0 += __expf(a[k].y);
        lsum0 += __expf(a[k].z); lsum0 += __expf(a[k].w);
    }
#pragma unroll
    for (int k = 0; k < 8; k++) {
        lsum1 += __expf(b[k].x); lsum1 += __expf(b[k].y);
        lsum1 += __expf(b[k].z); lsum1 += __expf(b[k].w);
    }

    float sel0 = 0.0f, nz0 = 0.0f, sel1 = 0.0f, nz1 = 0.0f;
    if (glab != 0) {
        float e = __expf(gval);
        if (which == 0) { sel0 = e; nz0 = 1.0f; }
        else            { sel1 = e; nz1 = 1.0f; }
    }

    // ---- 5. ONE combined block reduction of 6 values ----
    float r0 = warp_sum(lsum0);
    float r1 = warp_sum(lsum1);
    float r2 = warp_sum(sel0);
    float r3 = warp_sum(sel1);
    float r4 = warp_sum(nz0);
    float r5 = warp_sum(nz1);
    if (l == 0) {
        sh[0][w] = r0; sh[1][w] = r1; sh[2][w] = r2;
        sh[3][w] = r3; sh[4][w] = r4; sh[5][w] = r5;
    }
    __syncthreads();
    if (tid < 32) {
        const int NW = BDIM / 32;
        float z0 = (tid < NW) ? sh[0][tid] : 0.0f;
        float z1 = (tid < NW) ? sh[1][tid] : 0.0f;
        float s0 = (tid < NW) ? sh[2][tid] : 0.0f;
        float s1 = (tid < NW) ? sh[3][tid] : 0.0f;
        float c0 = (tid < NW) ? sh[4][tid] : 0.0f;
        float c1 = (tid < NW) ? sh[5][tid] : 0.0f;
        z0 = warp_sum(z0); z1 = warp_sum(z1);
        s0 = warp_sum(s0); s1 = warp_sum(s1);
        c0 = warp_sum(c0); c1 = warp_sum(c1);
        if (tid == 0) {
            int nl0 = s_lab0[X];
            int nl1 = s_lab1[X];
            bool k0 = (nl0 - (X - (int)(c0 + 0.5f))) > 0;
            bool k1 = (nl1 - (X - (int)(c1 + 0.5f))) > 0;
            float per0 = -__logf(s0 / z0 + 1e-5f);
            float per1 = -__logf(s1 / z1 + 1e-5f);
            g_row[2 * pair]     = make_float2(k0 ? per0 : 0.0f, k0 ? 1.0f : 0.0f);
            g_row[2 * pair + 1] = make_float2(k1 ? per1 : 0.0f, k1 ? 1.0f : 0.0f);
        }
    }

    // ---- 6. last-CTA global reduction ----
    if (tid == 0) {
        __threadfence();
        unsigned int n = atomicAdd(&g_done, 1u);
        s_last = (n == (unsigned int)(gridDim.x - 1)) ? 1 : 0;
    }
    __syncthreads();
    if (!s_last) return;
    __threadfence();   // acquire

    float s = 0.0f, c2 = 0.0f;
    const float4* r4p = (const float4*)g_row;   // 2 rows per float4
    const int nv = npairs;                      // (2*npairs rows) / 2
#pragma unroll 8
    for (int i = tid; i < nv; i += BDIM) {
        float4 v = r4p[i];
        s  += v.x + v.z;
        c2 += v.y + v.w;
    }
    s  = warp_sum(s);
    c2 = warp_sum(c2);
    __syncthreads();
    if (l == 0) { sh[0][w] = s; sh[1][w] = c2; }
    __syncthreads();
    if (tid < 32) {
        float x  = (tid < BDIM / 32) ? sh[0][tid] : 0.0f;
        float cc = (tid < BDIM / 32) ? sh[1][tid] : 0.0f;
        x  = warp_sum(x);
        cc = warp_sum(cc);
        if (tid == 0) {
            out[0] = x / fmaxf(cc, 1.0f);
            g_done = 0;                      // reset for next graph replay
        }
    }
}

// Generic fallback (any nlabels / odd B).
__global__ void __launch_bounds__(BDIM)
fused_generic(const float* __restrict__ prd, const int* __restrict__ tgt,
              float* __restrict__ out, int nlabels, int xc, int B)
{
    __shared__ float shf[BDIM / 32];
    __shared__ float shs[BDIM / 32];
    __shared__ float shc[BDIM / 32];
    __shared__ int   s_last;

    const int row = blockIdx.x;
    const int tid = threadIdx.x;
    const int w   = tid >> 5;
    const int l   = tid & 31;

    const float* p    = prd + (size_t)row * nlabels;
    const int*   trow = tgt + (size_t)row * xc;
    const int    X    = xc - 1;

    float lsum = 0.0f;
    for (int i = tid; i < nlabels; i += BDIM) lsum += __expf(p[i]);

    float sel = 0.0f, nzf = 0.0f;
    for (int j = tid; j < X; j += BDIM) {
        int lab = trow[j];
        if (lab != 0) { sel += __expf(p[lab]); nzf += 1.0f; }
    }

    float a = warp_sum(lsum), b = warp_sum(sel), c = warp_sum(nzf);
    if (l == 0) { shf[w] = a; shs[w] = b; shc[w] = c; }
    __syncthreads();
    if (tid < 32) {
        float x  = (tid < BDIM / 32) ? shf[tid] : 0.0f;
        float y  = (tid < BDIM / 32) ? shs[tid] : 0.0f;
        float cc = (tid < BDIM / 32) ? shc[tid] : 0.0f;
        x = warp_sum(x); y = warp_sum(y); cc = warp_sum(cc);
        if (tid == 0) {
            int num_listed = trow[X];
            int ignored    = X - (int)(cc + 0.5f);
            bool keep      = (num_listed - ignored) > 0;
            float per      = -__logf(y / x + 1e-5f);
            g_row[row] = make_float2(keep ? per : 0.0f, keep ? 1.0f : 0.0f);
        }
    }
    if (tid == 0) {
        __threadfence();
        unsigned int n = atomicAdd(&g_done, 1u);
        s_last = (n == (unsigned int)(gridDim.x - 1)) ? 1 : 0;
    }
    __syncthreads();
    if (!s_last) return;
    __threadfence();

    float s = 0.0f, c2 = 0.0f;
    for (int i = tid; i < B; i += BDIM) {
        float2 v = g_row[i];
        s += v.x; c2 += v.y;
    }
    s = warp_sum(s); c2 = warp_sum(c2);
    __syncthreads();
    if (l == 0) { shf[w] = s; shs[w] = c2; }
    __syncthreads();
    if (tid < 32) {
        float x  = (tid < BDIM / 32) ? shf[tid] : 0.0f;
        float cc = (tid < BDIM / 32) ? shs[tid] : 0.0f;
        x = warp_sum(x); cc = warp_sum(cc);
        if (tid == 0) { out[0] = x / fmaxf(cc, 1.0f); g_done = 0; }
    }
}

extern "C" void kernel_launch(void* const* d_in, const int* in_sizes, int n_in,
                              void* d_out, int out_size)
{
    const float* prd = (const float*)d_in[0];
    const int*   tgt = (const int*)d_in[1];

    const int xc = 51;                               // X=50 labels + count col
    const int B  = in_sizes[1] / xc;
    const int nlabels = (int)((long long)in_sizes[0] / B);

    if (nlabels == 8192 && (B & 1) == 0)
        fused_kernel<8192><<<B / 2, BDIM>>>(prd, tgt, (float*)d_out, xc, B / 2);
    else
        fused_generic<<<B, BDIM>>>(prd, tgt, (float*)d_out, nlabels, xc, B);
}

// round 6
// speedup vs baseline: 1.1077x; 1.0235x over previous
#include <cuda_runtime.h>
#include <math.h>

#define BDIM   256
#define STAGES 3
#define MAXB   65536

// Scratch (allocation-free): per-row {loss, keep} packed + arrival counter.
__device__ float2       g_row[MAXB];
__device__ unsigned int g_done = 0;

__device__ __forceinline__ float warp_sum(float v) {
#pragma unroll
    for (int o = 16; o > 0; o >>= 1)
        v += __shfl_xor_sync(0xffffffffu, v, o);
    return v;
}

__device__ __forceinline__ unsigned int smem_u32(const void* p) {
    return (unsigned int)__cvta_generic_to_shared(p);
}

__device__ __forceinline__ void mbar_init(unsigned int mb, unsigned int cnt) {
    asm volatile("mbarrier.init.shared.b64 [%0], %1;" :: "r"(mb), "r"(cnt) : "memory");
}
__device__ __forceinline__ void mbar_expect_tx(unsigned int mb, unsigned int bytes) {
    asm volatile("mbarrier.arrive.expect_tx.shared.b64 _, [%0], %1;"
                 :: "r"(mb), "r"(bytes) : "memory");
}
__device__ __forceinline__ void bulk_g2s(unsigned int dst, const void* src,
                                         unsigned int bytes, unsigned int mb) {
    asm volatile(
        "cp.async.bulk.shared::cta.global.mbarrier::complete_tx::bytes [%0], [%1], %2, [%3];"
        :: "r"(dst), "l"(src), "r"(bytes), "r"(mb) : "memory");
}
__device__ __forceinline__ void mbar_wait(unsigned int mb, unsigned int parity) {
    asm volatile(
        "{\n\t"
        ".reg .pred P;\n\t"
        "WAIT_%=:\n\t"
        "mbarrier.try_wait.parity.acquire.cta.shared::cta.b64 P, [%0], %1, 0x989680;\n\t"
        "@P bra.uni DONE_%=;\n\t"
        "bra.uni WAIT_%=;\n\t"
        "DONE_%=:\n\t"
        "}"
        :: "r"(mb), "r"(parity) : "memory");
}

// Persistent CTA, 3-stage cp.async.bulk pipeline through smem.
// Each CTA owns a contiguous range of rows; one 32KB bulk copy per row keeps
// the memory system saturated while warps compute exp/gather from smem.
template <int NL>
__global__ void __launch_bounds__(BDIM, 2)
pers_kernel(const float* __restrict__ prd, const int* __restrict__ tgt,
            float* __restrict__ out, int xc, int B, int G)
{
    constexpr int ROW_BYTES = NL * 4;          // 32768
    constexpr int ROW_F4    = NL / 4;          // 2048 float4

    extern __shared__ float4 stage[];          // STAGES * ROW_F4

    __shared__ __align__(8) unsigned long long mbar_store[STAGES];
    __shared__ float sh[2][3][BDIM / 32];      // [row parity][val][warp]
    __shared__ int   s_nl[2];
    __shared__ int   s_last;

    const int tid = threadIdx.x;
    const int w   = tid >> 5;
    const int l   = tid & 31;
    const int X   = xc - 1;
    const int bid = blockIdx.x;

    // row range for this CTA
    const int per   = B / G;
    const int rem   = B % G;
    const int start = bid * per + (bid < rem ? bid : rem);
    const int cnt   = per + (bid < rem ? 1 : 0);

    unsigned int mb[STAGES];
#pragma unroll
    for (int s = 0; s < STAGES; s++) mb[s] = smem_u32(&mbar_store[s]);

    if (tid == 0) {
#pragma unroll
        for (int s = 0; s < STAGES; s++) mbar_init(mb[s], 1);
    }
    __syncthreads();

    // initial prefetch: rows start..start+STAGES-1
    if (tid == 0) {
#pragma unroll
        for (int j = 0; j < STAGES; j++) {
            if (j < cnt) {
                mbar_expect_tx(mb[j], ROW_BYTES);
                bulk_g2s(smem_u32(stage + j * ROW_F4),
                         prd + (size_t)(start + j) * NL, ROW_BYTES, mb[j]);
            }
        }
    }

    // labels for row 0 of this CTA (prefetched one row ahead thereafter)
    int labv = 0;
    if (tid <= X && cnt > 0) labv = tgt[(size_t)start * xc + tid];

    int s = 0, ph = 0, wraps = 0;
    for (int i = 0; i < cnt; i++) {
        mbar_wait(mb[s], ph);

        // prefetch next row's labels (latency hides under exp phase)
        int labn = 0;
        if (tid <= X && (i + 1) < cnt)
            labn = tgt[(size_t)(start + i + 1) * xc + tid];

        const float4* rowp = stage + s * ROW_F4;
        const float*  rowf = (const float*)rowp;

        // exp-sum of the whole row from smem
        float lsum = 0.0f;
#pragma unroll
        for (int k = 0; k < 8; k++) {
            float4 v = rowp[tid + k * BDIM];
            lsum += __expf(v.x); lsum += __expf(v.y);
            lsum += __expf(v.z); lsum += __expf(v.w);
        }

        // label gather straight from smem (row is resident)
        float sel = 0.0f, nzf = 0.0f;
        if (tid < X && labv != 0) {
            sel = __expf(rowf[labv]);
            nzf = 1.0f;
        }
        if (tid == X) s_nl[i & 1] = labv;      // num_listed

        // combined block reduction (double-buffered by row parity)
        float r0 = warp_sum(lsum);
        float r1 = warp_sum(sel);
        float r2 = warp_sum(nzf);
        if (l == 0) {
            sh[i & 1][0][w] = r0;
            sh[i & 1][1][w] = r1;
            sh[i & 1][2][w] = r2;
        }
        __syncthreads();   // all reads of stage s complete past this point

        // refill stage s with row i+STAGES (issued while warp0 finalizes)
        if (tid == 0 && (i + STAGES) < cnt) {
            mbar_expect_tx(mb[s], ROW_BYTES);
            bulk_g2s(smem_u32(stage + s * ROW_F4),
                     prd + (size_t)(start + i + STAGES) * NL, ROW_BYTES, mb[s]);
        }

        if (tid < 32) {
            const int NW = BDIM / 32;
            float z  = (tid < NW) ? sh[i & 1][0][tid] : 0.0f;
            float y  = (tid < NW) ? sh[i & 1][1][tid] : 0.0f;
            float cc = (tid < NW) ? sh[i & 1][2][tid] : 0.0f;
            z  = warp_sum(z);
            y  = warp_sum(y);
            cc = warp_sum(cc);
            if (tid == 0) {
                int num_listed = s_nl[i & 1];
                int ignored    = X - (int)(cc + 0.5f);
                bool keep      = (num_listed - ignored) > 0;
                float per_row  = -__logf(y / z + 1e-5f);
                g_row[start + i] = make_float2(keep ? per_row : 0.0f,
                                               keep ? 1.0f : 0.0f);
            }
        }

        labv = labn;
        if (++s == STAGES) { s = 0; wraps ^= 1; ph = wraps; }
        else               { ph = wraps; }
    }

    // ---- last-CTA global reduction ----
    if (tid == 0) {
        __threadfence();
        unsigned int n = atomicAdd(&g_done, 1u);
        s_last = (n == (unsigned int)(G - 1)) ? 1 : 0;
    }
    __syncthreads();
    if (!s_last) return;
    __threadfence();   // acquire

    float ssum = 0.0f, csum = 0.0f;
    const float4* r4p = (const float4*)g_row;   // 2 rows per float4
    const int nv = B >> 1;
#pragma unroll 8
    for (int i = tid; i < nv; i += BDIM) {
        float4 v = r4p[i];
        ssum += v.x + v.z;
        csum += v.y + v.w;
    }
    ssum = warp_sum(ssum);
    csum = warp_sum(csum);
    __syncthreads();
    if (l == 0) { sh[0][0][w] = ssum; sh[0][1][w] = csum; }
    __syncthreads();
    if (tid < 32) {
        float x  = (tid < BDIM / 32) ? sh[0][0][tid] : 0.0f;
        float cc = (tid < BDIM / 32) ? sh[0][1][tid] : 0.0f;
        x  = warp_sum(x);
        cc = warp_sum(cc);
        if (tid == 0) {
            out[0] = x / fmaxf(cc, 1.0f);
            g_done = 0;                      // reset for next graph replay
        }
    }
}

// Generic fallback (any nlabels).
__global__ void __launch_bounds__(BDIM)
fused_generic(const float* __restrict__ prd, const int* __restrict__ tgt,
              float* __restrict__ out, int nlabels, int xc, int B)
{
    __shared__ float shf[BDIM / 32];
    __shared__ float shs[BDIM / 32];
    __shared__ float shc[BDIM / 32];
    __shared__ int   s_last;

    const int row = blockIdx.x;
    const int tid = threadIdx.x;
    const int w   = tid >> 5;
    const int l   = tid & 31;

    const float* p    = prd + (size_t)row * nlabels;
    const int*   trow = tgt + (size_t)row * xc;
    const int    X    = xc - 1;

    float lsum = 0.0f;
    for (int i = tid; i < nlabels; i += BDIM) lsum += __expf(p[i]);

    float sel = 0.0f, nzf = 0.0f;
    for (int j = tid; j < X; j += BDIM) {
        int lab = trow[j];
        if (lab != 0) { sel += __expf(p[lab]); nzf += 1.0f; }
    }

    float a = warp_sum(lsum), b = warp_sum(sel), c = warp_sum(nzf);
    if (l == 0) { shf[w] = a; shs[w] = b; shc[w] = c; }
    __syncthreads();
    if (tid < 32) {
        float x  = (tid < BDIM / 32) ? shf[tid] : 0.0f;
        float y  = (tid < BDIM / 32) ? shs[tid] : 0.0f;
        float cc = (tid < BDIM / 32) ? shc[tid] : 0.0f;
        x = warp_sum(x); y = warp_sum(y); cc = warp_sum(cc);
        if (tid == 0) {
            int num_listed = trow[X];
            int ignored    = X - (int)(cc + 0.5f);
            bool keep      = (num_listed - ignored) > 0;
            float per      = -__logf(y / x + 1e-5f);
            g_row[row] = make_float2(keep ? per : 0.0f, keep ? 1.0f : 0.0f);
        }
    }
    if (tid == 0) {
        __threadfence();
        unsigned int n = atomicAdd(&g_done, 1u);
        s_last = (n == (unsigned int)(gridDim.x - 1)) ? 1 : 0;
    }
    __syncthreads();
    if (!s_last) return;
    __threadfence();

    float s = 0.0f, c2 = 0.0f;
    for (int i = tid; i < B; i += BDIM) {
        float2 v = g_row[i];
        s += v.x; c2 += v.y;
    }
    s = warp_sum(s); c2 = warp_sum(c2);
    __syncthreads();
    if (l == 0) { shf[w] = s; shs[w] = c2; }
    __syncthreads();
    if (tid < 32) {
        float x  = (tid < BDIM / 32) ? shf[tid] : 0.0f;
        float cc = (tid < BDIM / 32) ? shs[tid] : 0.0f;
        x = warp_sum(x); cc = warp_sum(cc);
        if (tid == 0) { out[0] = x / fmaxf(cc, 1.0f); g_done = 0; }
    }
}

extern "C" void kernel_launch(void* const* d_in, const int* in_sizes, int n_in,
                              void* d_out, int out_size)
{
    const float* prd = (const float*)d_in[0];
    const int*   tgt = (const int*)d_in[1];

    const int xc = 51;                               // X=50 labels + count col
    const int B  = in_sizes[1] / xc;
    const int nlabels = (int)((long long)in_sizes[0] / B);

    if (nlabels == 8192) {
        int sms = 148;
        cudaDeviceGetAttribute(&sms, cudaDevAttrMultiProcessorCount, 0);
        int G = 2 * sms;
        if (G > B) G = B;
        size_t dyn = (size_t)STAGES * 8192 * sizeof(float);   // 96 KB
        cudaFuncSetAttribute(pers_kernel<8192>,
                             cudaFuncAttributeMaxDynamicSharedMemorySize, (int)dyn);
        pers_kernel<8192><<<G, BDIM, dyn>>>(prd, tgt, (float*)d_out, xc, B, G);
    } else {
        fused_generic<<<B, BDIM>>>(prd, tgt, (float*)d_out, nlabels, xc, B);
    }
}

// round 7
// speedup vs baseline: 1.1256x; 1.0162x over previous
#include <cuda_runtime.h>
#include <math.h>

#define BDIM   256
#define STAGES 3
#define MAXG   4096

// Scratch (allocation-free): per-CTA partial {loss_sum, keep_count}.
__device__ float2       g_part[MAXG];
__device__ unsigned int g_done = 0;

__device__ __forceinline__ float warp_sum(float v) {
#pragma unroll
    for (int o = 16; o > 0; o >>= 1)
        v += __shfl_xor_sync(0xffffffffu, v, o);
    return v;
}

__device__ __forceinline__ unsigned int smem_u32(const void* p) {
    return (unsigned int)__cvta_generic_to_shared(p);
}
__device__ __forceinline__ void mbar_init(unsigned int mb, unsigned int cnt) {
    asm volatile("mbarrier.init.shared.b64 [%0], %1;" :: "r"(mb), "r"(cnt) : "memory");
}
__device__ __forceinline__ void mbar_expect_tx(unsigned int mb, unsigned int bytes) {
    asm volatile("mbarrier.arrive.expect_tx.shared.b64 _, [%0], %1;"
                 :: "r"(mb), "r"(bytes) : "memory");
}
__device__ __forceinline__ void bulk_g2s(unsigned int dst, const void* src,
                                         unsigned int bytes, unsigned int mb) {
    asm volatile(
        "cp.async.bulk.shared::cta.global.mbarrier::complete_tx::bytes [%0], [%1], %2, [%3];"
        :: "r"(dst), "l"(src), "r"(bytes), "r"(mb) : "memory");
}
__device__ __forceinline__ void mbar_wait(unsigned int mb, unsigned int parity) {
    asm volatile(
        "{\n\t"
        ".reg .pred P;\n\t"
        "WAIT_%=:\n\t"
        "mbarrier.try_wait.parity.acquire.cta.shared::cta.b64 P, [%0], %1, 0x989680;\n\t"
        "@P bra.uni DONE_%=;\n\t"
        "bra.uni WAIT_%=;\n\t"
        "DONE_%=:\n\t"
        "}"
        :: "r"(mb), "r"(parity) : "memory");
}

// Persistent CTA, 3-stage cp.async.bulk pipeline through smem.
// Per-CTA loss/keep accumulate in registers; one global write per CTA.
template <int NL>
__global__ void __launch_bounds__(BDIM, 2)
pers_kernel(const float* __restrict__ prd, const int* __restrict__ tgt,
            float* __restrict__ out, int xc, int B, int G)
{
    constexpr int ROW_BYTES = NL * 4;          // 32768
    constexpr int ROW_F4    = NL / 4;          // 2048 float4

    extern __shared__ float4 stage[];          // STAGES * ROW_F4

    __shared__ __align__(8) unsigned long long mbar_store[STAGES];
    __shared__ float sh[2][2][BDIM / 32];      // [row parity][{z,sel}][warp]
    __shared__ int   shn[2][BDIM / 32];        // [row parity][warp] nz counts
    __shared__ int   s_nl[2];
    __shared__ int   s_last;

    const int tid = threadIdx.x;
    const int w   = tid >> 5;
    const int l   = tid & 31;
    const int X   = xc - 1;
    const int bid = blockIdx.x;

    // row range for this CTA
    const int per   = B / G;
    const int rem   = B % G;
    const int start = bid * per + (bid < rem ? bid : rem);
    const int cnt   = per + (bid < rem ? 1 : 0);

    unsigned int mb[STAGES];
#pragma unroll
    for (int s = 0; s < STAGES; s++) mb[s] = smem_u32(&mbar_store[s]);

    if (tid == 0) {
#pragma unroll
        for (int s = 0; s < STAGES; s++) mbar_init(mb[s], 1);
    }
    __syncthreads();

    // initial prefetch: rows start..start+STAGES-1
    if (tid == 0) {
#pragma unroll
        for (int j = 0; j < STAGES; j++) {
            if (j < cnt) {
                mbar_expect_tx(mb[j], ROW_BYTES);
                bulk_g2s(smem_u32(stage + j * ROW_F4),
                         prd + (size_t)(start + j) * NL, ROW_BYTES, mb[j]);
            }
        }
    }

    // labels for the first row (prefetched one row ahead thereafter)
    int labv = 0;
    if (tid <= X && cnt > 0) labv = tgt[(size_t)start * xc + tid];

    float acc_loss = 0.0f;   // meaningful in thread 0 only
    float acc_keep = 0.0f;

    int s = 0, ph = 0, wraps = 0;
    for (int i = 0; i < cnt; i++) {
        mbar_wait(mb[s], ph);

        // prefetch next row's labels (latency hides under exp phase)
        int labn = 0;
        if (tid <= X && (i + 1) < cnt)
            labn = tgt[(size_t)(start + i + 1) * xc + tid];

        const float4* rowp = stage + s * ROW_F4;
        const float*  rowf = (const float*)rowp;

        // exp-sum of the whole row from smem
        float lsum = 0.0f;
#pragma unroll
        for (int k = 0; k < 8; k++) {
            float4 v = rowp[tid + k * BDIM];
            lsum += __expf(v.x); lsum += __expf(v.y);
            lsum += __expf(v.z); lsum += __expf(v.w);
        }

        // label gather straight from smem (row is resident)
        bool  hit = (tid < X) && (labv != 0);
        float sel = hit ? __expf(rowf[labv]) : 0.0f;
        if (tid == X) s_nl[i & 1] = labv;      // num_listed

        // per-row block reduction: 2 float warp-sums + ballot popc
        float r0 = warp_sum(lsum);
        float r1 = warp_sum(sel);
        unsigned int bal = __ballot_sync(0xffffffffu, hit);
        if (l == 0) {
            sh[i & 1][0][w] = r0;
            sh[i & 1][1][w] = r1;
            shn[i & 1][w]   = __popc(bal);
        }
        __syncthreads();   // all reads of stage s complete past this point

        // refill stage s with row i+STAGES
        if (tid == 0 && (i + STAGES) < cnt) {
            mbar_expect_tx(mb[s], ROW_BYTES);
            bulk_g2s(smem_u32(stage + s * ROW_F4),
                     prd + (size_t)(start + i + STAGES) * NL, ROW_BYTES, mb[s]);
        }

        if (tid < 32) {
            const int NW = BDIM / 32;
            float z  = (tid < NW) ? sh[i & 1][0][tid] : 0.0f;
            float y  = (tid < NW) ? sh[i & 1][1][tid] : 0.0f;
            int   ni = (tid < NW) ? shn[i & 1][tid]   : 0;
            z = warp_sum(z);
            y = warp_sum(y);
#pragma unroll
            for (int o = 16; o > 0; o >>= 1)
                ni += __shfl_xor_sync(0xffffffffu, ni, o);
            if (tid == 0) {
                int num_listed = s_nl[i & 1];
                int ignored    = X - ni;
                bool keep      = (num_listed - ignored) > 0;
                if (keep) {
                    acc_loss += -__logf(y / z + 1e-5f);
                    acc_keep += 1.0f;
                }
            }
        }

        labv = labn;
        if (++s == STAGES) { s = 0; wraps ^= 1; }
        ph = wraps;
    }

    // ---- one global write per CTA, then last-CTA tiny reduce ----
    if (tid == 0) {
        g_part[bid] = make_float2(acc_loss, acc_keep);
        __threadfence();
        unsigned int n = atomicAdd(&g_done, 1u);
        s_last = (n == (unsigned int)(G - 1)) ? 1 : 0;
    }
    __syncthreads();
    if (!s_last) return;
    __threadfence();   // acquire

    float ssum = 0.0f, csum = 0.0f;
    for (int i = tid; i < G; i += BDIM) {
        float2 v = g_part[i];
        ssum += v.x;
        csum += v.y;
    }
    ssum = warp_sum(ssum);
    csum = warp_sum(csum);
    __syncthreads();
    if (l == 0) { sh[0][0][w] = ssum; sh[0][1][w] = csum; }
    __syncthreads();
    if (tid < 32) {
        float x  = (tid < BDIM / 32) ? sh[0][0][tid] : 0.0f;
        float cc = (tid < BDIM / 32) ? sh[0][1][tid] : 0.0f;
        x  = warp_sum(x);
        cc = warp_sum(cc);
        if (tid == 0) {
            out[0] = x / fmaxf(cc, 1.0f);
            g_done = 0;                      // reset for next graph replay
        }
    }
}

// Generic fallback (any nlabels).
__device__ float2       g_row_fb[65536];
__global__ void __launch_bounds__(BDIM)
fused_generic(const float* __restrict__ prd, const int* __restrict__ tgt,
              float* __restrict__ out, int nlabels, int xc, int B)
{
    __shared__ float shf[BDIM / 32];
    __shared__ float shs[BDIM / 32];
    __shared__ float shc[BDIM / 32];
    __shared__ int   s_last;

    const int row = blockIdx.x;
    const int tid = threadIdx.x;
    const int w   = tid >> 5;
    const int l   = tid & 31;

    const float* p    = prd + (size_t)row * nlabels;
    const int*   trow = tgt + (size_t)row * xc;
    const int    X    = xc - 1;

    float lsum = 0.0f;
    for (int i = tid; i < nlabels; i += BDIM) lsum += __expf(p[i]);

    float sel = 0.0f, nzf = 0.0f;
    for (int j = tid; j < X; j += BDIM) {
        int lab = trow[j];
        if (lab != 0) { sel += __expf(p[lab]); nzf += 1.0f; }
    }

    float a = warp_sum(lsum), b = warp_sum(sel), c = warp_sum(nzf);
    if (l == 0) { shf[w] = a; shs[w] = b; shc[w] = c; }
    __syncthreads();
    if (tid < 32) {
        float x  = (tid < BDIM / 32) ? shf[tid] : 0.0f;
        float y  = (tid < BDIM / 32) ? shs[tid] : 0.0f;
        float cc = (tid < BDIM / 32) ? shc[tid] : 0.0f;
        x = warp_sum(x); y = warp_sum(y); cc = warp_sum(cc);
        if (tid == 0) {
            int num_listed = trow[X];
            int ignored    = X - (int)(cc + 0.5f);
            bool keep      = (num_listed - ignored) > 0;
            float per      = -__logf(y / x + 1e-5f);
            g_row_fb[row] = make_float2(keep ? per : 0.0f, keep ? 1.0f : 0.0f);
        }
    }
    if (tid == 0) {
        __threadfence();
        unsigned int n = atomicAdd(&g_done, 1u);
        s_last = (n == (unsigned int)(gridDim.x - 1)) ? 1 : 0;
    }
    __syncthreads();
    if (!s_last) return;
    __threadfence();

    float s = 0.0f, c2 = 0.0f;
    for (int i = tid; i < B; i += BDIM) {
        float2 v = g_row_fb[i];
        s += v.x; c2 += v.y;
    }
    s = warp_sum(s); c2 = warp_sum(c2);
    __syncthreads();
    if (l == 0) { shf[w] = s; shs[w] = c2; }
    __syncthreads();
    if (tid < 32) {
        float x  = (tid < BDIM / 32) ? shf[tid] : 0.0f;
        float cc = (tid < BDIM / 32) ? shs[tid] : 0.0f;
        x = warp_sum(x); cc = warp_sum(cc);
        if (tid == 0) { out[0] = x / fmaxf(cc, 1.0f); g_done = 0; }
    }
}

extern "C" void kernel_launch(void* const* d_in, const int* in_sizes, int n_in,
                              void* d_out, int out_size)
{
    const float* prd = (const float*)d_in[0];
    const int*   tgt = (const int*)d_in[1];

    const int xc = 51;                               // X=50 labels + count col
    const int B  = in_sizes[1] / xc;
    const int nlabels = (int)((long long)in_sizes[0] / B);

    if (nlabels == 8192) {
        int sms = 148;
        cudaDeviceGetAttribute(&sms, cudaDevAttrMultiProcessorCount, 0);
        int G = 2 * sms;
        if (G > B)    G = B;
        if (G > MAXG) G = MAXG;
        size_t dyn = (size_t)STAGES * 8192 * sizeof(float);   // 96 KB
        cudaFuncSetAttribute(pers_kernel<8192>,
                             cudaFuncAttributeMaxDynamicSharedMemorySize, (int)dyn);
        pers_kernel<8192><<<G, BDIM, dyn>>>(prd, tgt, (float*)d_out, xc, B, G);
    } else {
        fused_generic<<<B, BDIM>>>(prd, tgt, (float*)d_out, nlabels, xc, B);
    }
}